// round 2
// baseline (speedup 1.0000x reference)
#include <cuda_runtime.h>
#include <cstdint>

// out[r,t] = sum_{k=0}^{K-1} kernel[K-1-k] * u[r, t+k]
// Fast path: two batch rows packed into f32x2 lanes, 8 consecutive outputs per
// thread via a register ring window, packed fma.rn.f32x2, swizzle-padded SMEM
// for conflict-free refills.

#define BLOCK 256
#define OPT   8
#define TT    (BLOCK * OPT)      // 2048 outputs per block (per row pair)
#define KMAX  128
#define LOADN (TT + KMAX)        // 2176 input positions staged per block

typedef unsigned long long ull;

__device__ __forceinline__ ull fma2(ull a, ull b, ull c) {
    ull d;
    asm("fma.rn.f32x2 %0, %1, %2, %3;" : "=l"(d) : "l"(a), "l"(b), "l"(c));
    return d;
}

// pad 1 float2 per 16 -> stride-8-float2 accesses become a perfect bank permutation
__device__ __forceinline__ int slot(int i) { return i + (i >> 4); }

__global__ __launch_bounds__(BLOCK)
void conv2row(const float* __restrict__ u, const float* __restrict__ kern,
              float* __restrict__ out, int T_out, int T_in, int K)
{
    __shared__ float2 s_u[LOADN + (LOADN >> 4) + 2];  // padded layout
    __shared__ float2 s_w[KMAX];

    const int tid  = threadIdx.x;
    const int base = blockIdx.x * TT;
    const long r0  = (long)blockIdx.y * 2;
    const float* __restrict__ u0 = u + r0 * (long)T_in;
    const float* __restrict__ u1 = u0 + T_in;

    // reversed kernel, broadcast-packed (w,w); zero padded to KMAX
    for (int i = tid; i < KMAX; i += BLOCK) {
        float w = (i < K) ? kern[K - 1 - i] : 0.0f;
        s_w[i] = make_float2(w, w);
    }

    // stage input tile: s_u[i] = (u0[base+i], u1[base+i]); zero beyond row end
    for (int i = tid * 4; i < LOADN; i += BLOCK * 4) {
        int g = base + i;
        float4 a, b;
        if (g + 3 < T_in) {
            a = *(const float4*)(u0 + g);
            b = *(const float4*)(u1 + g);
        } else {
            float av[4], bv[4];
            #pragma unroll
            for (int e = 0; e < 4; ++e) {
                int gg = g + e;
                av[e] = (gg < T_in) ? u0[gg] : 0.0f;
                bv[e] = (gg < T_in) ? u1[gg] : 0.0f;
            }
            a = make_float4(av[0], av[1], av[2], av[3]);
            b = make_float4(bv[0], bv[1], bv[2], bv[3]);
        }
        s_u[slot(i + 0)] = make_float2(a.x, b.x);
        s_u[slot(i + 1)] = make_float2(a.y, b.y);
        s_u[slot(i + 2)] = make_float2(a.z, b.z);
        s_u[slot(i + 3)] = make_float2(a.w, b.w);
    }
    __syncthreads();

    const int toff = tid * OPT;

    ull acc[OPT];
    #pragma unroll
    for (int i = 0; i < OPT; ++i) acc[i] = 0ull;

    // ring window: win[(p + j) & 7] holds input position toff + p + j
    ull win[8];
    #pragma unroll
    for (int j = 0; j < 8; ++j) win[j] = *(const ull*)&s_u[slot(toff + j)];

    const int nfull = K >> 3;
    const int rem   = K & 7;
    int k = 0;

    for (int it = 0; it < nfull; ++it, k += 8) {
        #pragma unroll
        for (int kk2 = 0; kk2 < 4; ++kk2) {
            // two packed weights per 16B shared load
            ulonglong2 wp = *(const ulonglong2*)&s_w[k + 2 * kk2];
            {
                const int kk = 2 * kk2;
                #pragma unroll
                for (int i = 0; i < OPT; ++i)
                    acc[i] = fma2(wp.x, win[(kk + i) & 7], acc[i]);
                win[kk] = *(const ull*)&s_u[slot(toff + k + kk + 8)];
            }
            {
                const int kk = 2 * kk2 + 1;
                #pragma unroll
                for (int i = 0; i < OPT; ++i)
                    acc[i] = fma2(wp.y, win[(kk + i) & 7], acc[i]);
                win[kk] = *(const ull*)&s_u[slot(toff + k + kk + 8)];
            }
        }
    }
    // remainder (rem < 8), same body, predicated; refill stays in bounds
    #pragma unroll
    for (int kk = 0; kk < 7; ++kk) {
        if (kk < rem) {
            ull wv = *(const ull*)&s_w[k + kk];
            #pragma unroll
            for (int i = 0; i < OPT; ++i)
                acc[i] = fma2(wv, win[(kk + i) & 7], acc[i]);
            win[kk] = *(const ull*)&s_u[slot(toff + k + kk + 8)];
        }
    }

    // store: row r0 gets .x lane, row r0+1 gets .y lane
    float2 res[OPT];
    #pragma unroll
    for (int i = 0; i < OPT; ++i) res[i] = *(float2*)&acc[i];

    const long o0 = r0 * (long)T_out;
    const int  t0 = base + toff;
    if (t0 + OPT <= T_out) {
        float4* p0 = (float4*)(out + o0 + t0);
        float4* p1 = (float4*)(out + o0 + T_out + t0);
        p0[0] = make_float4(res[0].x, res[1].x, res[2].x, res[3].x);
        p0[1] = make_float4(res[4].x, res[5].x, res[6].x, res[7].x);
        p1[0] = make_float4(res[0].y, res[1].y, res[2].y, res[3].y);
        p1[1] = make_float4(res[4].y, res[5].y, res[6].y, res[7].y);
    } else {
        #pragma unroll
        for (int i = 0; i < OPT; ++i) {
            int t = t0 + i;
            if (t < T_out) {
                out[o0 + t]         = res[i].x;
                out[o0 + T_out + t] = res[i].y;
            }
        }
    }
}

// Robust fallback for any shape the fast path doesn't cover.
__global__ void conv_naive(const float* __restrict__ u, const float* __restrict__ kern,
                           float* __restrict__ out, int T_out, int T_in, int K, long total)
{
    long idx = (long)blockIdx.x * blockDim.x + threadIdx.x;
    if (idx >= total) return;
    int  t = (int)(idx % T_out);
    long r = idx / T_out;
    const float* up = u + r * (long)T_in + t;
    float acc = 0.0f;
    for (int k = 0; k < K; ++k)
        acc = fmaf(kern[K - 1 - k], up[k], acc);
    out[idx] = acc;
}

extern "C" void kernel_launch(void* const* d_in, const int* in_sizes, int n_in,
                              void* d_out, int out_size)
{
    const float* u    = (const float*)d_in[0];
    const float* kern = (const float*)d_in[1];
    float*       out  = (float*)d_out;

    const long n_u   = in_sizes[0];
    const int  K     = in_sizes[1];
    const long n_out = out_size;

    // u is (R, T_out + K - 1), out is (R, T_out)  =>  R = (n_u - n_out)/(K-1)
    long R = 1;
    if (K > 1 && (n_u - n_out) % (K - 1) == 0) {
        long r = (n_u - n_out) / (K - 1);
        if (r > 0 && n_out % r == 0 && n_u % r == 0) R = r;
    } else if (K == 1 && n_u == n_out) {
        R = 1;  // degenerate: T_in == T_out, any row split works; treat as 1 row
    }
    const int T_out = (int)(n_out / R);
    const int T_in  = (int)(n_u / R);

    const bool fast = (K >= 1) && (K <= KMAX) && (R % 2 == 0) &&
                      (T_in % 4 == 0) && (T_out % 4 == 0) &&
                      (R * (long)T_out == n_out) && (R * (long)T_in == n_u) &&
                      (T_in >= T_out + K - 1);

    if (fast) {
        dim3 grid((T_out + TT - 1) / TT, (unsigned)(R / 2));
        conv2row<<<grid, BLOCK>>>(u, kern, out, T_out, T_in, K);
    } else {
        long total = n_out;
        int  thr = 256;
        long blocks = (total + thr - 1) / thr;
        conv_naive<<<(unsigned)blocks, thr>>>(u, kern, out, T_out, T_in, K, total);
    }
}